// round 6
// baseline (speedup 1.0000x reference)
#include <cuda_runtime.h>
#include <cuda_bf16.h>
#include <math.h>

// ResidualVectorQuantizer: x [1024,128,128] f32, codebooks [4,256,128] f32.
// N = 131072 rows, D = 128, 4 levels x 256 codes.
//
// Algebra:
//   argmax_k cos-sim = argmax_k dot(r, e_n[k]);  s = that max dot (exactly).
//   loss_lvl = 1.25/(N*D) * sum_n (||r_n||^2 - s_n^2)   (e_n unit to ~1e-9)
//   x_q = x - residual_final
//
// Output fp32 concat: [x_q (16777216) | mean_loss (1) | indices (524288) | scalars (524288)]

#define NROWS   131072
#define DIM     128
#define KCODES  256
#define LEVELS  4
#define M_TILE  128
#define NTHREADS 512
#define EPITCH  260   // e_s[d][k] pitch (floats): mult of 4; epilogue gather 4-way max
#define RPITCH  132   // r_s[row][d] pitch (floats): mult of 4 for LDS.128
#define EPS_F   1e-8f

#define XQ_ELEMS   (NROWS * DIM)
#define IDX_ELEMS  (NROWS * LEVELS)
#define FULL_OUT   (XQ_ELEMS + 1 + 2 * IDX_ELEMS)
#define NBLOCKS    (NROWS / M_TILE)     // 1024

__device__ float g_en_t[LEVELS * DIM * KCODES];  // normalized codebooks, TRANSPOSED [lvl][d][k]
__device__ float g_part[NBLOCKS];                // per-block loss partials (deterministic)

// ---------------------------------------------------------------------------
// Packed fp32x2 FMA (Blackwell FFMA2; only reachable via PTX f32x2)
// ---------------------------------------------------------------------------
__device__ __forceinline__ void fma2(unsigned long long& acc,
                                     unsigned long long a, unsigned long long b) {
    asm("fma.rn.f32x2 %0, %1, %2, %0;" : "+l"(acc) : "l"(a), "l"(b));
}
__device__ __forceinline__ unsigned long long pack2(float v) {
    unsigned long long r;
    asm("mov.b64 %0, {%1, %1};" : "=l"(r) : "f"(v));
    return r;
}
__device__ __forceinline__ float lo32(unsigned long long v) {
    return __uint_as_float((unsigned)v);
}
__device__ __forceinline__ float hi32(unsigned long long v) {
    return __uint_as_float((unsigned)(v >> 32));
}

union F4 { float4 f; unsigned long long u[2]; float s[4]; };

// ---------------------------------------------------------------------------
// Prep: normalize codebook rows, write TRANSPOSED g_en_t[lvl][d][k].
// ---------------------------------------------------------------------------
__global__ void rvq_prep_kernel(const float* __restrict__ cb) {
    int row  = blockIdx.x * 8 + (threadIdx.x >> 5);   // 128 blocks x 8 warps = 1024 rows
    int lane = threadIdx.x & 31;
    if (row >= LEVELS * KCODES) return;
    int lvl = row >> 8, k = row & 255;

    const float* src = cb + row * DIM;
    float v[4]; float ss = 0.0f;
#pragma unroll
    for (int j = 0; j < 4; j++) { v[j] = src[lane + 32 * j]; ss += v[j] * v[j]; }
#pragma unroll
    for (int off = 16; off; off >>= 1) ss += __shfl_xor_sync(0xFFFFFFFFu, ss, off);
    float inv = 1.0f / (sqrtf(ss) + EPS_F);
    float* dst = g_en_t + lvl * DIM * KCODES + k;
#pragma unroll
    for (int j = 0; j < 4; j++) dst[(lane + 32 * j) * KCODES] = v[j] * inv;
}

// ---------------------------------------------------------------------------
// Main fused kernel: 1024 blocks x 512 threads, 128 rows/block, 8 rows/warp.
// Per level: staged-codebook GEMM (FFMA2, 8 rows x 8 codes per thread),
// warp argmax, rank-1 residual update, deterministic loss partials.
// ---------------------------------------------------------------------------
__global__ __launch_bounds__(NTHREADS, 1)
void rvq_main_kernel(const float* __restrict__ x, float* __restrict__ out, int out_size) {
    extern __shared__ float sm[];
    float* e_s = sm;                      // [DIM][EPITCH]
    float* r_s = sm + DIM * EPITCH;       // [M_TILE][RPITCH]
    __shared__ float s_wloss[16];

    const int tid = threadIdx.x;
    const int tx  = tid & 31;
    const int ty  = tid >> 5;             // warp id (0..15)
    const int row0  = blockIdx.x * M_TILE;
    const int wrow0 = ty * 8;

    const bool full_out = (out_size >= FULL_OUT);
    float* out_idx = out + XQ_ELEMS + 1;
    float* out_s   = out + XQ_ELEMS + 1 + IDX_ELEMS;

    // Load x tile into residual smem (coalesced float4).
    for (int i = tid; i < M_TILE * DIM / 4; i += NTHREADS) {
        int r = i >> 5, dg = i & 31;
        *(float4*)&r_s[r * RPITCH + 4 * dg] = *(const float4*)&x[(row0 + r) * DIM + 4 * dg];
    }

    // Hoisted smem bases for the mainloop.
    const float* rbase = r_s + wrow0 * RPITCH;       // this warp's 8 rows
    const float* ebase = e_s + 4 * tx;               // this lane's code column

    float loss_acc = 0.0f;

    for (int lvl = 0; lvl < LEVELS; lvl++) {
        __syncthreads();   // previous level's e_s fully consumed by all warps
        // Stage codebook level: pure coalesced float4 copy (pre-transposed).
        const float* gsrc = g_en_t + lvl * DIM * KCODES;
        for (int i = tid; i < DIM * KCODES / 4; i += NTHREADS) {
            int flat = 4 * i;
            int d = flat >> 8, k = flat & 255;
            *(float4*)&e_s[d * EPITCH + k] = *(const float4*)&gsrc[flat];
        }
        __syncthreads();

        // --- GEMM: thread owns rows wrow0..+7, codes {4tx..+3, 128+4tx..+3} ---
        unsigned long long acc2[8][4];
#pragma unroll
        for (int a = 0; a < 8; a++)
#pragma unroll
            for (int p = 0; p < 4; p++) acc2[a][p] = 0ULL;

#pragma unroll 2
        for (int d0 = 0; d0 < DIM; d0 += 4) {
#pragma unroll
            for (int g = 0; g < 2; g++) {          // row groups of 4 (reg pressure)
                F4 rf[4];
#pragma unroll
                for (int a = 0; a < 4; a++)
                    rf[a].f = *(const float4*)&rbase[(4 * g + a) * RPITCH + d0];
#pragma unroll
                for (int dd = 0; dd < 4; dd++) {
                    F4 ea, eb;
                    ea.f = *(const float4*)&ebase[(d0 + dd) * EPITCH];
                    eb.f = *(const float4*)&ebase[(d0 + dd) * EPITCH + 128];
#pragma unroll
                    for (int a = 0; a < 4; a++) {
                        unsigned long long rp = pack2(rf[a].s[dd]);
                        int ai = 4 * g + a;
                        fma2(acc2[ai][0], rp, ea.u[0]);
                        fma2(acc2[ai][1], rp, ea.u[1]);
                        fma2(acc2[ai][2], rp, eb.u[0]);
                        fma2(acc2[ai][3], rp, eb.u[1]);
                    }
                }
            }
        }

        // --- Epilogue per row ---
#pragma unroll
        for (int a = 0; a < 8; a++) {
            // Unpack 8 candidate dots (ascending code order within thread).
            float v[8];
            int   c[8];
#pragma unroll
            for (int p = 0; p < 4; p++) {
                int base = (p < 2) ? (4 * tx + 2 * p) : (128 + 4 * tx + 2 * (p - 2));
                v[2 * p]     = lo32(acc2[a][p]); c[2 * p]     = base;
                v[2 * p + 1] = hi32(acc2[a][p]); c[2 * p + 1] = base + 1;
            }
            float best = v[0]; int bidx = c[0];
#pragma unroll
            for (int j = 1; j < 8; j++)
                if (v[j] > best) { best = v[j]; bidx = c[j]; }
            // Cross-lane argmax; tie -> smaller index (jnp first-occurrence).
#pragma unroll
            for (int off = 16; off; off >>= 1) {
                float ov = __shfl_xor_sync(0xFFFFFFFFu, best, off);
                int   oi = __shfl_xor_sync(0xFFFFFFFFu, bidx, off);
                if (ov > best || (ov == best && oi < bidx)) { best = ov; bidx = oi; }
            }
            // s = best.  ||r||^2 BEFORE the rank-1 update:
            float p = 0.0f;
#pragma unroll
            for (int m = 0; m < 4; m++) {
                float rv = r_s[(wrow0 + a) * RPITCH + tx + 32 * m];
                p += rv * rv;
            }
#pragma unroll
            for (int off = 16; off; off >>= 1)
                p += __shfl_xor_sync(0xFFFFFFFFu, p, off);
            if (tx == 0) loss_acc += (p - best * best);

            // Rank-1 update: r -= s * e_n[bidx]  (warp-private rows; no race)
#pragma unroll
            for (int m = 0; m < 4; m++) {
                int d = tx + 32 * m;
                r_s[(wrow0 + a) * RPITCH + d] -= best * e_s[d * EPITCH + bidx];
            }

            if (full_out && tx == 0) {
                int grow = row0 + wrow0 + a;
                out_idx[grow * LEVELS + lvl] = (float)bidx;
                out_s[grow * LEVELS + lvl]   = best;
            }
        }
    }

    // Deterministic in-block loss reduction.
    if (tx == 0) s_wloss[ty] = loss_acc;
    __syncthreads();
    if (tid == 0) {
        float t = 0.0f;
#pragma unroll
        for (int w = 0; w < 16; w++) t += s_wloss[w];
        g_part[blockIdx.x] = t;
    }

    // x_q = x - residual_final (coalesced float4; sync above covers r_s).
    for (int i = tid; i < M_TILE * DIM / 4; i += NTHREADS) {
        int r = i >> 5, dg = i & 31;
        float4 xv = *(const float4*)&x[(row0 + r) * DIM + 4 * dg];
        float4 rv = *(const float4*)&r_s[r * RPITCH + 4 * dg];
        float4 o; o.x = xv.x - rv.x; o.y = xv.y - rv.y;
        o.z = xv.z - rv.z; o.w = xv.w - rv.w;
        *(float4*)&out[(row0 + r) * DIM + 4 * dg] = o;
    }
}

// ---------------------------------------------------------------------------
// Finalize: deterministic fixed-order reduction of 1024 partials.
// mean_loss = 1.25 / (4 * N * D) * total
// ---------------------------------------------------------------------------
__global__ void rvq_finalize_kernel(float* __restrict__ out, int out_size) {
    int lane = threadIdx.x;
    float t = 0.0f;
    for (int j = 0; j < NBLOCKS / 32; j++)       // fixed order: 32 chunks per lane
        t += g_part[lane * (NBLOCKS / 32) + j];
#pragma unroll
    for (int off = 16; off; off >>= 1)
        t += __shfl_xor_sync(0xFFFFFFFFu, t, off);
    if (lane == 0 && out_size >= FULL_OUT)
        out[XQ_ELEMS] = t * (1.25f / (4.0f * (float)NROWS * (float)DIM));
}

extern "C" void kernel_launch(void* const* d_in, const int* in_sizes, int n_in,
                              void* d_out, int out_size) {
    const float* x  = (const float*)d_in[0];
    const float* cb = (const float*)d_in[1];
    float* out = (float*)d_out;

    const int smem_bytes = (DIM * EPITCH + M_TILE * RPITCH) * sizeof(float);  // 200704
    cudaFuncSetAttribute(rvq_main_kernel,
                         cudaFuncAttributeMaxDynamicSharedMemorySize, smem_bytes);

    rvq_prep_kernel<<<128, 256>>>(cb);
    rvq_main_kernel<<<NBLOCKS, NTHREADS, smem_bytes>>>(x, out, out_size);
    rvq_finalize_kernel<<<1, 32>>>(out, out_size);
}

// round 7
// speedup vs baseline: 1.0166x; 1.0166x over previous
#include <cuda_runtime.h>
#include <cuda_bf16.h>
#include <math.h>

// ResidualVectorQuantizer: x [1024,128,128] f32, codebooks [4,256,128] f32.
// N = 131072 rows, D = 128, 4 levels x 256 codes.
//
// Algebra:
//   argmax_k cos-sim = argmax_k dot(r, e_n[k]);  s = that max dot (exactly).
//   loss_lvl = 1.25/(N*D) * sum_n (||r_n||^2 - s_n^2);  ||r||^2 tracked
//   incrementally: ||r_{l+1}||^2 = ||r_l||^2 - s^2  (d unit).
//   x_q = x - residual_final
//
// Output fp32 concat: [x_q (16777216) | mean_loss (1) | indices (524288) | scalars (524288)]

#define NROWS   131072
#define DIM     128
#define KCODES  256
#define LEVELS  4
#define M_TILE  128
#define NTHREADS 512
#define EPITCH  260   // e_s[d][k] pitch (floats): mult of 4; epilogue gather 4-way max
#define RPITCH  132   // r_s[row][d] pitch (floats): mult of 4 for LDS.128
#define EPS_F   1e-8f

#define XQ_ELEMS   (NROWS * DIM)
#define IDX_ELEMS  (NROWS * LEVELS)
#define FULL_OUT   (XQ_ELEMS + 1 + 2 * IDX_ELEMS)
#define NBLOCKS    (NROWS / M_TILE)     // 1024

__device__ float g_en_t[LEVELS * DIM * KCODES];  // normalized codebooks, TRANSPOSED [lvl][d][k]
__device__ float g_part[NBLOCKS];                // per-block loss partials (deterministic)

// ---------------------------------------------------------------------------
// Packed fp32x2 FMA (Blackwell FFMA2; only reachable via PTX f32x2)
// ---------------------------------------------------------------------------
__device__ __forceinline__ void fma2(unsigned long long& acc,
                                     unsigned long long a, unsigned long long b) {
    asm("fma.rn.f32x2 %0, %1, %2, %0;" : "+l"(acc) : "l"(a), "l"(b));
}
__device__ __forceinline__ unsigned long long pack2(float v) {
    unsigned long long r;
    asm("mov.b64 %0, {%1, %1};" : "=l"(r) : "f"(v));
    return r;
}
__device__ __forceinline__ float lo32(unsigned long long v) {
    return __uint_as_float((unsigned)v);
}
__device__ __forceinline__ float hi32(unsigned long long v) {
    return __uint_as_float((unsigned)(v >> 32));
}

// cp.async 16B global->shared (LDGSTS): no register round-trip, overlappable.
__device__ __forceinline__ void cp_async16(void* smem_dst, const void* gsrc) {
    unsigned sdst = (unsigned)__cvta_generic_to_shared(smem_dst);
    asm volatile("cp.async.cg.shared.global [%0], [%1], 16;" :: "r"(sdst), "l"(gsrc));
}
#define CP_COMMIT()   asm volatile("cp.async.commit_group;")
#define CP_WAIT_ALL() asm volatile("cp.async.wait_group 0;")

union F4 { float4 f; unsigned long long u[2]; float s[4]; };

// ---------------------------------------------------------------------------
// Prep: normalize codebook rows, write TRANSPOSED g_en_t[lvl][d][k].
// ---------------------------------------------------------------------------
__global__ void rvq_prep_kernel(const float* __restrict__ cb) {
    int row  = blockIdx.x * 8 + (threadIdx.x >> 5);   // 128 blocks x 8 warps = 1024 rows
    int lane = threadIdx.x & 31;
    if (row >= LEVELS * KCODES) return;
    int lvl = row >> 8, k = row & 255;

    const float* src = cb + row * DIM;
    float v[4]; float ss = 0.0f;
#pragma unroll
    for (int j = 0; j < 4; j++) { v[j] = src[lane + 32 * j]; ss += v[j] * v[j]; }
#pragma unroll
    for (int off = 16; off; off >>= 1) ss += __shfl_xor_sync(0xFFFFFFFFu, ss, off);
    float inv = 1.0f / (sqrtf(ss) + EPS_F);
    float* dst = g_en_t + lvl * DIM * KCODES + k;
#pragma unroll
    for (int j = 0; j < 4; j++) dst[(lane + 32 * j) * KCODES] = v[j] * inv;
}

// ---------------------------------------------------------------------------
// Main fused kernel: 1024 blocks x 512 threads, 128 rows/block, 8 rows/warp.
// Per level: cp.async-staged codebook, FFMA2 GEMM (8 rows x 8 codes/thread),
// warp argmax, rank-1 residual update, incremental-norm loss.
// ---------------------------------------------------------------------------
__global__ __launch_bounds__(NTHREADS, 1)
void rvq_main_kernel(const float* __restrict__ x, float* __restrict__ out, int out_size) {
    extern __shared__ float sm[];
    float* e_s = sm;                      // [DIM][EPITCH]
    float* r_s = sm + DIM * EPITCH;       // [M_TILE][RPITCH]
    __shared__ float s_wloss[16];

    const int tid = threadIdx.x;
    const int tx  = tid & 31;
    const int ty  = tid >> 5;             // warp id (0..15)
    const int row0  = blockIdx.x * M_TILE;
    const int wrow0 = ty * 8;

    const bool full_out = (out_size >= FULL_OUT);
    float* out_idx = out + XQ_ELEMS + 1;
    float* out_s   = out + XQ_ELEMS + 1 + IDX_ELEMS;

    // Async-load x tile into residual smem (overlaps with level-0 staging).
    for (int i = tid; i < M_TILE * DIM / 4; i += NTHREADS) {
        int r = i >> 5, dg = i & 31;
        cp_async16(&r_s[r * RPITCH + 4 * dg], &x[(row0 + r) * DIM + 4 * dg]);
    }
    CP_COMMIT();

    // Hoisted smem bases for the mainloop.
    const float* rbase = r_s + wrow0 * RPITCH;       // this warp's 8 rows
    const float* ebase = e_s + 4 * tx;               // this lane's code column

    float nrm2[8];                // per-row ||r||^2, tracked incrementally
    float loss_acc = 0.0f;

    for (int lvl = 0; lvl < LEVELS; lvl++) {
        __syncthreads();   // previous level's e_s fully consumed by all warps
        // Stage codebook level via cp.async (pre-transposed, coalesced 16B).
        const float* gsrc = g_en_t + lvl * DIM * KCODES;
        for (int i = tid; i < DIM * KCODES / 4; i += NTHREADS) {
            int flat = 4 * i;
            int d = flat >> 8, k = flat & 255;
            cp_async16(&e_s[d * EPITCH + k], &gsrc[flat]);
        }
        CP_COMMIT();
        CP_WAIT_ALL();     // also covers the x-tile group at lvl 0
        __syncthreads();

        if (lvl == 0) {
            // One-time per-row ||x||^2 (r == x at level 0).
#pragma unroll
            for (int a = 0; a < 8; a++) {
                float p = 0.0f;
#pragma unroll
                for (int m = 0; m < 4; m++) {
                    float rv = rbase[a * RPITCH + tx + 32 * m];
                    p += rv * rv;
                }
#pragma unroll
                for (int off = 16; off; off >>= 1)
                    p += __shfl_xor_sync(0xFFFFFFFFu, p, off);
                nrm2[a] = p;
            }
        }

        // --- GEMM: thread owns rows wrow0..+7, codes {4tx..+3, 128+4tx..+3} ---
        unsigned long long acc2[8][4];
#pragma unroll
        for (int a = 0; a < 8; a++)
#pragma unroll
            for (int p = 0; p < 4; p++) acc2[a][p] = 0ULL;

#pragma unroll 2
        for (int d0 = 0; d0 < DIM; d0 += 4) {
#pragma unroll
            for (int g = 0; g < 2; g++) {          // row groups of 4 (reg pressure)
                F4 rf[4];
#pragma unroll
                for (int a = 0; a < 4; a++)
                    rf[a].f = *(const float4*)&rbase[(4 * g + a) * RPITCH + d0];
#pragma unroll
                for (int dd = 0; dd < 4; dd++) {
                    F4 ea, eb;
                    ea.f = *(const float4*)&ebase[(d0 + dd) * EPITCH];
                    eb.f = *(const float4*)&ebase[(d0 + dd) * EPITCH + 128];
#pragma unroll
                    for (int a = 0; a < 4; a++) {
                        unsigned long long rp = pack2(rf[a].s[dd]);
                        int ai = 4 * g + a;
                        fma2(acc2[ai][0], rp, ea.u[0]);
                        fma2(acc2[ai][1], rp, ea.u[1]);
                        fma2(acc2[ai][2], rp, eb.u[0]);
                        fma2(acc2[ai][3], rp, eb.u[1]);
                    }
                }
            }
        }

        // --- Epilogue per row ---
#pragma unroll
        for (int a = 0; a < 8; a++) {
            // Unpack 8 candidate dots (ascending code order within thread).
            float v[8];
            int   c[8];
#pragma unroll
            for (int p = 0; p < 4; p++) {
                int base = (p < 2) ? (4 * tx + 2 * p) : (128 + 4 * tx + 2 * (p - 2));
                v[2 * p]     = lo32(acc2[a][p]); c[2 * p]     = base;
                v[2 * p + 1] = hi32(acc2[a][p]); c[2 * p + 1] = base + 1;
            }
            float best = v[0]; int bidx = c[0];
#pragma unroll
            for (int j = 1; j < 8; j++)
                if (v[j] > best) { best = v[j]; bidx = c[j]; }
            // Cross-lane argmax; tie -> smaller index (jnp first-occurrence).
#pragma unroll
            for (int off = 16; off; off >>= 1) {
                float ov = __shfl_xor_sync(0xFFFFFFFFu, best, off);
                int   oi = __shfl_xor_sync(0xFFFFFFFFu, bidx, off);
                if (ov > best || (ov == best && oi < bidx)) { best = ov; bidx = oi; }
            }
            // s = best.  Loss uses ||r||^2 BEFORE the update; then decrement.
            if (tx == 0) loss_acc += (nrm2[a] - best * best);
            nrm2[a] -= best * best;

            // Rank-1 update: r -= s * e_n[bidx]  (warp-private rows; no race)
#pragma unroll
            for (int m = 0; m < 4; m++) {
                int d = tx + 32 * m;
                r_s[(wrow0 + a) * RPITCH + d] -= best * e_s[d * EPITCH + bidx];
            }

            if (full_out && tx == 0) {
                int grow = row0 + wrow0 + a;
                out_idx[grow * LEVELS + lvl] = (float)bidx;
                out_s[grow * LEVELS + lvl]   = best;
            }
        }
    }

    // Deterministic in-block loss reduction.
    if (tx == 0) s_wloss[ty] = loss_acc;
    __syncthreads();
    if (tid == 0) {
        float t = 0.0f;
#pragma unroll
        for (int w = 0; w < 16; w++) t += s_wloss[w];
        g_part[blockIdx.x] = t;
    }

    // x_q = x - residual_final (coalesced float4; sync above covers r_s).
    for (int i = tid; i < M_TILE * DIM / 4; i += NTHREADS) {
        int r = i >> 5, dg = i & 31;
        float4 xv = *(const float4*)&x[(row0 + r) * DIM + 4 * dg];
        float4 rv = *(const float4*)&r_s[r * RPITCH + 4 * dg];
        float4 o; o.x = xv.x - rv.x; o.y = xv.y - rv.y;
        o.z = xv.z - rv.z; o.w = xv.w - rv.w;
        *(float4*)&out[(row0 + r) * DIM + 4 * dg] = o;
    }
}

// ---------------------------------------------------------------------------
// Finalize: deterministic fixed-order reduction of 1024 partials.
// mean_loss = 1.25 / (4 * N * D) * total
// ---------------------------------------------------------------------------
__global__ void rvq_finalize_kernel(float* __restrict__ out, int out_size) {
    int lane = threadIdx.x;
    float t = 0.0f;
    for (int j = 0; j < NBLOCKS / 32; j++)       // fixed order: 32 chunks per lane
        t += g_part[lane * (NBLOCKS / 32) + j];
#pragma unroll
    for (int off = 16; off; off >>= 1)
        t += __shfl_xor_sync(0xFFFFFFFFu, t, off);
    if (lane == 0 && out_size >= FULL_OUT)
        out[XQ_ELEMS] = t * (1.25f / (4.0f * (float)NROWS * (float)DIM));
}

extern "C" void kernel_launch(void* const* d_in, const int* in_sizes, int n_in,
                              void* d_out, int out_size) {
    const float* x  = (const float*)d_in[0];
    const float* cb = (const float*)d_in[1];
    float* out = (float*)d_out;

    const int smem_bytes = (DIM * EPITCH + M_TILE * RPITCH) * sizeof(float);  // 200704
    cudaFuncSetAttribute(rvq_main_kernel,
                         cudaFuncAttributeMaxDynamicSharedMemorySize, smem_bytes);

    rvq_prep_kernel<<<128, 256>>>(cb);
    rvq_main_kernel<<<NBLOCKS, NTHREADS, smem_bytes>>>(x, out, out_size);
    rvq_finalize_kernel<<<1, 32>>>(out, out_size);
}

// round 9
// speedup vs baseline: 1.0260x; 1.0093x over previous
#include <cuda_runtime.h>
#include <cuda_bf16.h>
#include <math.h>

// ResidualVectorQuantizer: x [1024,128,128] f32, codebooks [4,256,128] f32.
// N = 131072 rows, D = 128, 4 levels x 256 codes.
//
// Algebra:
//   argmax_k cos-sim = argmax_k dot(r, e_n[k]);  s = that max dot (exactly).
//   loss_lvl = 1.25/(N*D) * sum_n (||r_n||^2 - s_n^2);  ||r||^2 tracked
//   incrementally: ||r_{l+1}||^2 = ||r_l||^2 - s^2  (d unit).
//   x_q = x - residual_final
//
// Output fp32 concat: [x_q (16777216) | mean_loss (1) | indices (524288) | scalars (524288)]

#define NROWS   131072
#define DIM     128
#define KCODES  256
#define LEVELS  4
#define M_TILE  128
#define NTHREADS 512
#define EPITCH  260   // e_s[d][k] pitch (floats): mult of 4; epilogue gather 4-way max
#define RPITCH  132   // r_s[row][d] pitch (floats): mult of 4 for LDS.128 / cp.async16
#define EPS_F   1e-8f

#define XQ_ELEMS   (NROWS * DIM)
#define IDX_ELEMS  (NROWS * LEVELS)
#define FULL_OUT   (XQ_ELEMS + 1 + 2 * IDX_ELEMS)
#define NBLOCKS    (NROWS / M_TILE)     // 1024

__device__ float g_en_t[LEVELS * DIM * KCODES];  // normalized codebooks, TRANSPOSED [lvl][d][k]
__device__ float g_part[NBLOCKS];                // per-block loss partials (deterministic)

// ---------------------------------------------------------------------------
// Packed fp32x2 FMA (Blackwell FFMA2; only reachable via PTX f32x2)
// ---------------------------------------------------------------------------
__device__ __forceinline__ void fma2(unsigned long long& acc,
                                     unsigned long long a, unsigned long long b) {
    asm("fma.rn.f32x2 %0, %1, %2, %0;" : "+l"(acc) : "l"(a), "l"(b));
}
__device__ __forceinline__ unsigned long long pack2(float v) {
    unsigned long long r;
    asm("mov.b64 %0, {%1, %1};" : "=l"(r) : "f"(v));
    return r;
}
__device__ __forceinline__ float lo32(unsigned long long v) {
    return __uint_as_float((unsigned)v);
}
__device__ __forceinline__ float hi32(unsigned long long v) {
    return __uint_as_float((unsigned)(v >> 32));
}

// cp.async 16B global->shared (LDGSTS): no register round-trip, overlappable.
__device__ __forceinline__ void cp_async16(void* smem_dst, const void* gsrc) {
    unsigned sdst = (unsigned)__cvta_generic_to_shared(smem_dst);
    asm volatile("cp.async.cg.shared.global [%0], [%1], 16;" :: "r"(sdst), "l"(gsrc));
}
#define CP_COMMIT()    asm volatile("cp.async.commit_group;")
#define CP_WAIT_ALL()  asm volatile("cp.async.wait_group 0;")
#define CP_WAIT_1()    asm volatile("cp.async.wait_group 1;")

union F4 { float4 f; unsigned long long u[2]; float s[4]; };

// ---------------------------------------------------------------------------
// Prep: normalize codebook rows, write TRANSPOSED g_en_t[lvl][d][k].
// ---------------------------------------------------------------------------
__global__ void rvq_prep_kernel(const float* __restrict__ cb) {
    int row  = blockIdx.x * 8 + (threadIdx.x >> 5);   // 128 blocks x 8 warps = 1024 rows
    int lane = threadIdx.x & 31;
    if (row >= LEVELS * KCODES) return;
    int lvl = row >> 8, k = row & 255;

    const float* src = cb + row * DIM;
    float v[4]; float ss = 0.0f;
#pragma unroll
    for (int j = 0; j < 4; j++) { v[j] = src[lane + 32 * j]; ss += v[j] * v[j]; }
#pragma unroll
    for (int off = 16; off; off >>= 1) ss += __shfl_xor_sync(0xFFFFFFFFu, ss, off);
    float inv = 1.0f / (sqrtf(ss) + EPS_F);
    float* dst = g_en_t + lvl * DIM * KCODES + k;
#pragma unroll
    for (int j = 0; j < 4; j++) dst[(lane + 32 * j) * KCODES] = v[j] * inv;
}

// ---------------------------------------------------------------------------
// Main fused kernel: 1024 blocks x 512 threads, 128 rows/block, 8 rows/warp.
// Per level: cp.async-staged codebook, FFMA2 GEMM (8 rows x 8 codes/thread,
// e-loads hoisted over full row set), warp argmax, rank-1 residual update,
// incremental-norm loss.
// ---------------------------------------------------------------------------
__global__ __launch_bounds__(NTHREADS, 1)
void rvq_main_kernel(const float* __restrict__ x, float* __restrict__ out, int out_size) {
    extern __shared__ float sm[];
    float* e_s = sm;                      // [DIM][EPITCH]
    float* r_s = sm + DIM * EPITCH;       // [M_TILE][RPITCH]
    __shared__ float s_wloss[16];

    const int tid = threadIdx.x;
    const int tx  = tid & 31;
    const int ty  = tid >> 5;             // warp id (0..15)
    const int row0  = blockIdx.x * M_TILE;
    const int wrow0 = ty * 8;

    const bool full_out = (out_size >= FULL_OUT);
    float* out_idx = out + XQ_ELEMS + 1;
    float* out_s   = out + XQ_ELEMS + 1 + IDX_ELEMS;

    // Async-load x tile into residual smem (own commit group).
    for (int i = tid; i < M_TILE * DIM / 4; i += NTHREADS) {
        int r = i >> 5, dg = i & 31;
        cp_async16(&r_s[r * RPITCH + 4 * dg], &x[(row0 + r) * DIM + 4 * dg]);
    }
    CP_COMMIT();

    // Hoisted smem bases for the mainloop.
    const float* rbase = r_s + wrow0 * RPITCH;       // this warp's 8 rows
    const float* ebase = e_s + 4 * tx;               // this lane's code column

    float nrm2[8];                // per-row ||r||^2, tracked incrementally
    float loss_acc = 0.0f;

    for (int lvl = 0; lvl < LEVELS; lvl++) {
        __syncthreads();   // previous level's e_s fully consumed by all warps
        // Stage codebook level via cp.async (pre-transposed, coalesced 16B).
        const float* gsrc = g_en_t + lvl * DIM * KCODES;
        for (int i = tid; i < DIM * KCODES / 4; i += NTHREADS) {
            int flat = 4 * i;
            int d = flat >> 8, k = flat & 255;
            cp_async16(&e_s[d * EPITCH + k], &gsrc[flat]);
        }
        CP_COMMIT();

        if (lvl == 0) {
            // x-tile group drained (e group may still be in flight); make the
            // x data visible across threads, then compute per-row ||x||^2
            // overlapped with the codebook stage.
            CP_WAIT_1();
            __syncthreads();
#pragma unroll
            for (int a = 0; a < 8; a++) {
                float p = 0.0f;
#pragma unroll
                for (int m = 0; m < 4; m++) {
                    float rv = rbase[a * RPITCH + tx + 32 * m];
                    p += rv * rv;
                }
#pragma unroll
                for (int off = 16; off; off >>= 1)
                    p += __shfl_xor_sync(0xFFFFFFFFu, p, off);
                nrm2[a] = p;
            }
        }

        CP_WAIT_ALL();
        __syncthreads();

        // --- GEMM: thread owns rows wrow0..+7, codes {4tx..+3, 128+4tx..+3} ---
        unsigned long long acc2[8][4];
#pragma unroll
        for (int a = 0; a < 8; a++)
#pragma unroll
            for (int p = 0; p < 4; p++) acc2[a][p] = 0ULL;

#pragma unroll 2
        for (int d0 = 0; d0 < DIM; d0 += 4) {
            F4 rf[8];
#pragma unroll
            for (int a = 0; a < 8; a++)
                rf[a].f = *(const float4*)&rbase[a * RPITCH + d0];
#pragma unroll
            for (int dd = 0; dd < 4; dd++) {
                F4 ea, eb;
                ea.f = *(const float4*)&ebase[(d0 + dd) * EPITCH];
                eb.f = *(const float4*)&ebase[(d0 + dd) * EPITCH + 128];
#pragma unroll
                for (int a = 0; a < 8; a++) {
                    unsigned long long rp = pack2(rf[a].s[dd]);
                    fma2(acc2[a][0], rp, ea.u[0]);
                    fma2(acc2[a][1], rp, ea.u[1]);
                    fma2(acc2[a][2], rp, eb.u[0]);
                    fma2(acc2[a][3], rp, eb.u[1]);
                }
            }
        }

        // --- Epilogue per row ---
#pragma unroll
        for (int a = 0; a < 8; a++) {
            // Unpack 8 candidate dots (ascending code order within thread).
            float v[8];
            int   c[8];
#pragma unroll
            for (int p = 0; p < 4; p++) {
                int base = (p < 2) ? (4 * tx + 2 * p) : (128 + 4 * tx + 2 * (p - 2));
                v[2 * p]     = lo32(acc2[a][p]); c[2 * p]     = base;
                v[2 * p + 1] = hi32(acc2[a][p]); c[2 * p + 1] = base + 1;
            }
            float best = v[0]; int bidx = c[0];
#pragma unroll
            for (int j = 1; j < 8; j++)
                if (v[j] > best) { best = v[j]; bidx = c[j]; }
            // Cross-lane argmax; tie -> smaller index (jnp first-occurrence).
#pragma unroll
            for (int off = 16; off; off >>= 1) {
                float ov = __shfl_xor_sync(0xFFFFFFFFu, best, off);
                int   oi = __shfl_xor_sync(0xFFFFFFFFu, bidx, off);
                if (ov > best || (ov == best && oi < bidx)) { best = ov; bidx = oi; }
            }
            // s = best.  Loss uses ||r||^2 BEFORE the update; then decrement.
            if (tx == 0) loss_acc += (nrm2[a] - best * best);
            nrm2[a] -= best * best;

            // Rank-1 update: r -= s * e_n[bidx]  (warp-private rows; no race)
#pragma unroll
            for (int m = 0; m < 4; m++) {
                int d = tx + 32 * m;
                r_s[(wrow0 + a) * RPITCH + d] -= best * e_s[d * EPITCH + bidx];
            }

            if (full_out && tx == 0) {
                int grow = row0 + wrow0 + a;
                out_idx[grow * LEVELS + lvl] = (float)bidx;
                out_s[grow * LEVELS + lvl]   = best;
            }
        }
    }

    // Deterministic in-block loss reduction.
    if (tx == 0) s_wloss[ty] = loss_acc;
    __syncthreads();
    if (tid == 0) {
        float t = 0.0f;
#pragma unroll
        for (int w = 0; w < 16; w++) t += s_wloss[w];
        g_part[blockIdx.x] = t;
    }

    // x_q = x - residual_final (coalesced float4; sync above covers r_s).
    for (int i = tid; i < M_TILE * DIM / 4; i += NTHREADS) {
        int r = i >> 5, dg = i & 31;
        float4 xv = *(const float4*)&x[(row0 + r) * DIM + 4 * dg];
        float4 rv = *(const float4*)&r_s[r * RPITCH + 4 * dg];
        float4 o; o.x = xv.x - rv.x; o.y = xv.y - rv.y;
        o.z = xv.z - rv.z; o.w = xv.w - rv.w;
        *(float4*)&out[(row0 + r) * DIM + 4 * dg] = o;
    }
}

// ---------------------------------------------------------------------------
// Finalize: deterministic fixed-order reduction of 1024 partials.
// mean_loss = 1.25 / (4 * N * D) * total
// ---------------------------------------------------------------------------
__global__ void rvq_finalize_kernel(float* __restrict__ out, int out_size) {
    int lane = threadIdx.x;
    float t = 0.0f;
    for (int j = 0; j < NBLOCKS / 32; j++)       // fixed order: 32 chunks per lane
        t += g_part[lane * (NBLOCKS / 32) + j];
#pragma unroll
    for (int off = 16; off; off >>= 1)
        t += __shfl_xor_sync(0xFFFFFFFFu, t, off);
    if (lane == 0 && out_size >= FULL_OUT)
        out[XQ_ELEMS] = t * (1.25f / (4.0f * (float)NROWS * (float)DIM));
}

extern "C" void kernel_launch(void* const* d_in, const int* in_sizes, int n_in,
                              void* d_out, int out_size) {
    const float* x  = (const float*)d_in[0];
    const float* cb = (const float*)d_in[1];
    float* out = (float*)d_out;

    const int smem_bytes = (DIM * EPITCH + M_TILE * RPITCH) * sizeof(float);  // 200704
    cudaFuncSetAttribute(rvq_main_kernel,
                         cudaFuncAttributeMaxDynamicSharedMemorySize, smem_bytes);

    rvq_prep_kernel<<<128, 256>>>(cb);
    rvq_main_kernel<<<NBLOCKS, NTHREADS, smem_bytes>>>(x, out, out_size);
    rvq_finalize_kernel<<<1, 32>>>(out, out_size);
}